// round 5
// baseline (speedup 1.0000x reference)
#include <cuda_runtime.h>
#include <cuda_bf16.h>

// P1 FEM evaluation on a structured 17x17 grid over [0,1]^2.
// Direct cell lookup replaces the reference's 512-triangle scan.
//
// Bitwise-faithful decision logic vs the JAX reference (validated in R4,
// rel_err 3.8e-8):
//  - Minv entries are exactly {+-16, 0}; x*16 is an exact exponent shift,
//    so (ux - floor(ux)) == 16*fl(X - xs[i]) bit-exactly.
//  - TOL = 1e-10 is below fp32 ulp on interior grid lines -> those points
//    fail every strict bbox test in the reference -> output 0 (`dead`).
//    x==0 / y==0 edges survive (bbox lower bound -1e-10 is representable).
//  - scan order = lower triangles then upper -> upper wins on the diagonal.
//
// R5 changes (latency/issue-bound profile, DRAM only 20%):
//  - weight table packed as float2 rows: 2x LDS.64 per point (was 4x LDS.32)
//  - 8 points/thread, loads front-batched (MLP=4 LDG.128), 2x STG.128 out
//  - 1024 blocks x 256 threads -> single wave on 148 SMs

static constexpr float TOLF = 1e-10f;

__device__ __forceinline__ float eval_point(float X, float Y,
                                            const float2* __restrict__ ws2) {
    float ux = X * 16.0f;              // exact (power-of-2 scale)
    float uy = Y * 16.0f;
    float fx = floorf(ux);
    float fy = floorf(uy);
    // Interior grid line -> reference's strict bbox test fails everywhere.
    bool dead = ((ux == fx) && (fx != 0.0f)) || ((uy == fy) && (fy != 0.0f));
    fx = fminf(fx, 15.0f);
    fy = fminf(fy, 15.0f);
    int i = (int)fx;
    int j = (int)fy;

    float dx16 = ux - fx;              // == 16 * fl(X - xs[i]) exactly
    float dy16 = uy - fy;              // == 16 * fl(Y - xs[j]) exactly

    // Lower triangle (v00, v10, v11):  s=(dx-dy)*16, t=dy*16
    float sl = dx16 - dy16;
    float tl = dy16;
    // Upper triangle (v00, v11, v01):  s=dx*16, t=(dy-dx)*16
    float su = dx16;
    float tu = dy16 - dx16;

    int v00 = i * 17 + j;              // vid = i*17 + j
    float2 a = ws2[v00];               // (w00, w01)
    float2 b = ws2[v00 + 17];          // (w10, w11)
    float w00 = a.x, w01 = a.y, w10 = b.x, w11 = b.y;

    float val = 0.0f;
    if ((sl > -TOLF) && (tl > -TOLF) && ((sl + tl) < 1.0f))
        val = (1.0f - sl - tl) * w00 + sl * w10 + tl * w11;
    if ((su > -TOLF) && (tu > -TOLF) && ((su + tu) < 1.0f))
        val = (1.0f - su - tu) * w00 + su * w11 + tu * w01;  // upper overrides
    return dead ? 0.0f : val;
}

__global__ void __launch_bounds__(256)
p1_eval_kernel(const float4* __restrict__ x4,
               const float*  __restrict__ w,
               float4*       __restrict__ out4) {
    // Packed weight table: ws2[i*17+j] = (w[i,j], w[i,j+1]); column j=16 unused.
    __shared__ float2 ws2[289];
    for (int t = threadIdx.x; t < 289; t += 256) {
        float lo = w[t];
        float hi = (t % 17 < 16) ? w[t + 1] : 0.0f;
        ws2[t] = make_float2(lo, hi);
    }
    __syncthreads();

    // Each thread: 8 points = 4 input float4, 2 output float4.
    int o0 = blockIdx.x * 512 + threadIdx.x;   // output float4 index
    int o1 = o0 + 256;

    // Front-batched loads (MLP = 4 independent LDG.128).
    float4 a0 = x4[2 * o0];
    float4 a1 = x4[2 * o0 + 1];
    float4 b0 = x4[2 * o1];
    float4 b1 = x4[2 * o1 + 1];

    float4 r0, r1;
    r0.x = eval_point(a0.x, a0.y, ws2);
    r0.y = eval_point(a0.z, a0.w, ws2);
    r0.z = eval_point(a1.x, a1.y, ws2);
    r0.w = eval_point(a1.z, a1.w, ws2);
    r1.x = eval_point(b0.x, b0.y, ws2);
    r1.y = eval_point(b0.z, b0.w, ws2);
    r1.z = eval_point(b1.x, b1.y, ws2);
    r1.w = eval_point(b1.z, b1.w, ws2);

    out4[o0] = r0;
    out4[o1] = r1;
}

extern "C" void kernel_launch(void* const* d_in, const int* in_sizes, int n_in,
                              void* d_out, int out_size) {
    // Identify inputs by element count: x = largest (4,194,304 floats),
    // weight = 289 floats.
    const float* x = nullptr;
    const float* w = nullptr;
    int max_sz = -1;
    for (int k = 0; k < n_in; k++) {
        if (in_sizes[k] == 289) w = (const float*)d_in[k];
        if (in_sizes[k] > max_sz) { max_sz = in_sizes[k]; x = (const float*)d_in[k]; }
    }

    // 2,097,152 points -> 524,288 output float4 -> 1024 blocks x 256 threads x 2.
    p1_eval_kernel<<<1024, 256>>>((const float4*)x, w, (float4*)d_out);
}